// round 2
// baseline (speedup 1.0000x reference)
#include <cuda_runtime.h>
#include <cstdint>

// state: [2, 4096, 512] float32. Composition of 4 CNOTs = one bit-twiddle
// permutation of the 4096 row indices; batch dim (512 floats) copied as-is.
// out[n, i, b] = in[n, src(i), b].

static __device__ __forceinline__ unsigned src_index(unsigned j) {
    // PAIRS applied in reverse for the source map (big-endian: qubit q -> bit 11-q)
    j ^= ((j >> 0) & 1u) << 4;    // (c=11, t=7)
    j ^= ((j >> 6) & 1u) << 9;    // (c=5,  t=2)
    j ^= ((j >> 9) & 1u) << 8;    // (c=2,  t=3)
    j ^= ((j >> 11) & 1u) << 10;  // (c=0,  t=1)
    return j;
}

// 2*4096 rows * 128 float4/row = 2^20 float4 total.
// 1024 blocks * 256 threads = 2^18 threads; each thread moves 4 float4s
// at stride 2^18 (independent loads -> MLP=4). Single wave on 148 SMs.
__global__ __launch_bounds__(256) void cnot_perm_copy4(
    const float4* __restrict__ in, float4* __restrict__ out)
{
    unsigned base = blockIdx.x * blockDim.x + threadIdx.x;  // 0 .. 2^18-1

    float4 v[4];
    unsigned dst[4];
    #pragma unroll
    for (int k = 0; k < 4; k++) {
        unsigned idx = base + (unsigned)k * (1u << 18);
        unsigned b4  = idx & 127u;       // float4 column in row
        unsigned row = idx >> 7;         // 0 .. 8191
        unsigned i   = row & 4095u;
        unsigned n   = row >> 12;
        unsigned src = src_index(i);
        v[k]   = in[(((n << 12) | src) << 7) | b4];
        dst[k] = idx;
    }
    #pragma unroll
    for (int k = 0; k < 4; k++)
        out[dst[k]] = v[k];
}

extern "C" void kernel_launch(void* const* d_in, const int* in_sizes, int n_in,
                              void* d_out, int out_size) {
    const float4* in  = (const float4*)d_in[0];
    float4*       out = (float4*)d_out;
    cnot_perm_copy4<<<1024, 256>>>(in, out);
}

// round 3
// speedup vs baseline: 1.0295x; 1.0295x over previous
#include <cuda_runtime.h>
#include <cstdint>

// state: [2, 4096, 512] float32. Composition of the 4 CNOTs is a pure
// row-index permutation (bit twiddle). out[g, :] = in[srcrow(g), :] where
// rows are 512 contiguous floats (2048 B).
//
// Engine: TMA bulk copies. Each CTA owns 8 destination rows; lane 0 enqueues
// 8 async 2KB loads (global->smem, mbarrier complete_tx), then as each
// arrives issues the bulk store (smem->global). 1024 CTAs put the whole
// 16 MB input in flight simultaneously.

static __device__ __forceinline__ unsigned src_index(unsigned j) {
    // PAIRS [(0,1),(2,3),(5,2),(11,7)] applied in reverse for the source map
    // (big-endian: qubit q -> bit 11-q)
    j ^= ((j >> 0) & 1u) << 4;    // (c=11, t=7)
    j ^= ((j >> 6) & 1u) << 9;    // (c=5,  t=2)
    j ^= ((j >> 9) & 1u) << 8;    // (c=2,  t=3)
    j ^= ((j >> 11) & 1u) << 10;  // (c=0,  t=1)
    return j;
}

#define ROWS_PER_BLK 8
#define ROW_BYTES 2048

__global__ __launch_bounds__(32) void cnot_tma_copy(
    const float* __restrict__ in, float* __restrict__ out)
{
    __shared__ alignas(128) unsigned char buf[ROWS_PER_BLK][ROW_BYTES];
    __shared__ alignas(8) unsigned long long mbar[ROWS_PER_BLK];

    if (threadIdx.x != 0) return;

    unsigned base_row = blockIdx.x * ROWS_PER_BLK;
    uint32_t mb0  = (uint32_t)__cvta_generic_to_shared(&mbar[0]);
    uint32_t sbuf = (uint32_t)__cvta_generic_to_shared(&buf[0][0]);

    #pragma unroll
    for (int j = 0; j < ROWS_PER_BLK; j++)
        asm volatile("mbarrier.init.shared.b64 [%0], 1;"
                     :: "r"(mb0 + 8u * j) : "memory");
    asm volatile("fence.proxy.async.shared::cta;" ::: "memory");

    // Enqueue all 8 row loads (deep MLP via the TMA engine).
    #pragma unroll
    for (int j = 0; j < ROWS_PER_BLK; j++) {
        unsigned g   = base_row + j;
        unsigned i   = g & 4095u;
        unsigned n   = g >> 12;
        unsigned src = (n << 12) | src_index(i);
        const float* gsrc = in + (size_t)src * 512u;
        asm volatile("mbarrier.arrive.expect_tx.shared.b64 _, [%0], %1;"
                     :: "r"(mb0 + 8u * j), "r"((unsigned)ROW_BYTES) : "memory");
        asm volatile(
            "cp.async.bulk.shared::cta.global.mbarrier::complete_tx::bytes "
            "[%0], [%1], %2, [%3];"
            :: "r"(sbuf + (unsigned)j * ROW_BYTES), "l"(gsrc),
               "r"((unsigned)ROW_BYTES), "r"(mb0 + 8u * j)
            : "memory");
    }

    // As each load lands, push it back out with a bulk store.
    #pragma unroll
    for (int j = 0; j < ROWS_PER_BLK; j++) {
        uint32_t mb = mb0 + 8u * j;
        asm volatile(
            "{\n\t.reg .pred P;\n\t"
            "W%=:\n\t"
            "mbarrier.try_wait.parity.acquire.cta.shared::cta.b64 P, [%0], 0;\n\t"
            "@P bra D%=;\n\t"
            "bra W%=;\n\t"
            "D%=:\n\t}"
            :: "r"(mb) : "memory");
        unsigned g = base_row + j;
        float* gdst = out + (size_t)g * 512u;
        asm volatile(
            "cp.async.bulk.global.shared::cta.bulk_group [%0], [%1], %2;"
            :: "l"(gdst), "r"(sbuf + (unsigned)j * ROW_BYTES),
               "r"((unsigned)ROW_BYTES)
            : "memory");
    }
    asm volatile("cp.async.bulk.commit_group;" ::: "memory");
    asm volatile("cp.async.bulk.wait_group 0;" ::: "memory");
}

extern "C" void kernel_launch(void* const* d_in, const int* in_sizes, int n_in,
                              void* d_out, int out_size) {
    const float* in  = (const float*)d_in[0];
    float*       out = (float*)d_out;
    // 8192 rows total / 8 rows per block = 1024 blocks
    cnot_tma_copy<<<1024, 32>>>(in, out);
}